// round 2
// baseline (speedup 1.0000x reference)
#include <cuda_runtime.h>
#include <cstdint>

// Problem constants (CRF_6262062317593): B=512, S=512, T=128
#define CRF_B 512
#define CRF_S 512
#define CRF_T 128

// Scratch (device globals: allocations are forbidden).
__device__ float g_diff[CRF_B];
__device__ int   g_tags_is64;
__device__ int   g_mask_is32;

// ---------------------------------------------------------------------------
// Detect element width of tags (int64 vs int32) and mask (int32 vs uint8).
// tags values are in [0,128): if int64, every odd 32-bit word is 0.
// mask values are 0/1: if int32, every 32-bit word is <=1; if uint8 (all-ones
// dataset), words look like 0x01010101 > 1.
// Reads only 512B / 256B — safe under either layout. Deterministic.
// ---------------------------------------------------------------------------
__global__ void crf_detect_kernel(const void* __restrict__ tags,
                                  const void* __restrict__ mask)
{
    const unsigned int* tw = (const unsigned int*)tags;
    int zeros = 0;
    for (int k = 0; k < 64; k++)
        if (tw[2 * k + 1] == 0u) zeros++;
    g_tags_is64 = (zeros >= 48) ? 1 : 0;

    const unsigned int* mw = (const unsigned int*)mask;
    int big = 0;
    for (int k = 0; k < 64; k++)
        if (mw[k] > 1u) big++;
    g_mask_is32 = (big == 0) ? 1 : 0;
}

// ---------------------------------------------------------------------------
// One CTA per batch element, T=128 threads (thread j owns tag j).
// Forward recursion in exp-space: next_j = log(sum_i exp(s_i - m) * E_ij) + m
// with E = exp(transitions) register-resident per column, and m = previous
// step's tag-0 score (uniform shift; exact logsumexp, just a different,
// still-safe normalizer since within-CTA score spread is O(10)).
// ---------------------------------------------------------------------------
__global__ __launch_bounds__(CRF_T)
void crf_fwd_kernel(const float* __restrict__ em,       // (B,S,T) f32
                    const void*  __restrict__ tags,     // (B,S) i32 or i64
                    const void*  __restrict__ mask,     // (B,S) i32 or u8
                    const float* __restrict__ startT,   // (T)
                    const float* __restrict__ endT,     // (T)
                    const float* __restrict__ trans)    // (T,T)
{
    const int b = blockIdx.x;
    const int j = threadIdx.x;
    const int lane = j & 31;
    const int warp = j >> 5;

    const float* __restrict__ emb = em + (size_t)b * CRF_S * CRF_T;

    __shared__ float         sExp[CRF_T];
    __shared__ float         sM;                 // uniform shift for exp
    __shared__ float         sRed[4];
    __shared__ float         sRed2[4];
    __shared__ float         sPart[CRF_T];
    __shared__ int           sCnt[CRF_T];
    __shared__ float         sFwd;
    __shared__ unsigned char sMask[CRF_S];
    __shared__ short         sTags[CRF_S];

    // ---- stage mask + tags rows into smem with detected widths ----
    if (g_mask_is32) {
        const int* m32 = (const int*)mask + (size_t)b * CRF_S;
        for (int s = j; s < CRF_S; s += CRF_T) sMask[s] = (m32[s] != 0);
    } else {
        const unsigned char* m8 = (const unsigned char*)mask + (size_t)b * CRF_S;
        for (int s = j; s < CRF_S; s += CRF_T) sMask[s] = (m8[s] != 0);
    }
    if (g_tags_is64) {
        const long long* t64 = (const long long*)tags + (size_t)b * CRF_S;
        for (int s = j; s < CRF_S; s += CRF_T) sTags[s] = (short)t64[s];
    } else {
        const int* t32 = (const int*)tags + (size_t)b * CRF_S;
        for (int s = j; s < CRF_S; s += CRF_T) sTags[s] = (short)t32[s];
    }

    // ---- register-resident column j of E = exp(transitions) ----
    float Ecol[CRF_T];
#pragma unroll
    for (int i = 0; i < CRF_T; i++)
        Ecol[i] = __expf(trans[i * CRF_T + j]);

    // t = 0
    float score = startT[j] + emb[j];
    if (j == 0) sM = score;

    const float4* sE4 = (const float4*)sExp;

    for (int s = 1; s < CRF_S; s++) {
        __syncthreads();               // sM + previous sExp reads complete
        const float m = sM;
        sExp[j] = __expf(score - m);
        __syncthreads();               // sExp ready

        float a0 = 0.f, a1 = 0.f, a2 = 0.f, a3 = 0.f;
#pragma unroll
        for (int i = 0; i < CRF_T / 4; i++) {
            const float4 e = sE4[i];
            a0 = fmaf(e.x, Ecol[4 * i + 0], a0);
            a1 = fmaf(e.y, Ecol[4 * i + 1], a1);
            a2 = fmaf(e.z, Ecol[4 * i + 2], a2);
            a3 = fmaf(e.w, Ecol[4 * i + 3], a3);
        }
        const float sum = (a0 + a1) + (a2 + a3);

        const float ns = __logf(sum) + m + emb[(size_t)s * CRF_T + j];
        score = sMask[s] ? ns : score;
        if (j == 0) sM = score;        // safe: all warps passed 2nd barrier
    }

    // ---- final logsumexp(score + endT), exact max-based (runs once) ----
    score += endT[j];
    __syncthreads();
    {
        float v = score;
#pragma unroll
        for (int off = 16; off; off >>= 1)
            v = fmaxf(v, __shfl_xor_sync(0xffffffffu, v, off));
        if (lane == 0) sRed[warp] = v;
        __syncthreads();
        const float m = fmaxf(fmaxf(sRed[0], sRed[1]), fmaxf(sRed[2], sRed[3]));
        float e = __expf(score - m);
#pragma unroll
        for (int off = 16; off; off >>= 1)
            e += __shfl_xor_sync(0xffffffffu, e, off);
        if (lane == 0) sRed2[warp] = e;
        __syncthreads();
        if (j == 0) {
            const float tot = (sRed2[0] + sRed2[1]) + (sRed2[2] + sRed2[3]);
            sFwd = __logf(tot) + m;
        }
    }

    // ---- gold score (parallel over timesteps, fixed-order tree reduce) ----
    float part = 0.f;
    int cnt = 0;
    for (int s = j; s < CRF_S; s += CRF_T) {
        const int mk = sMask[s] ? 1 : 0;
        cnt += mk;
        if (s >= 1 && mk) {
            const int tp = (int)sTags[s - 1];
            const int tc = (int)sTags[s];
            part += trans[tp * CRF_T + tc] + emb[(size_t)s * CRF_T + tc];
        }
    }
    sPart[j] = part;
    sCnt[j]  = cnt;
    __syncthreads();
#pragma unroll
    for (int stride = CRF_T / 2; stride > 0; stride >>= 1) {
        if (j < stride) {
            sPart[j] += sPart[j + stride];
            sCnt[j]  += sCnt[j + stride];
        }
        __syncthreads();
    }
    if (j == 0) {
        const int t0 = (int)sTags[0];
        float gold = sPart[0] + startT[t0] + emb[t0];
        const int seq_end = sCnt[0] - 1;
        gold += endT[(int)sTags[seq_end]];
        g_diff[b] = sFwd - gold;
    }
}

// Deterministic tree reduction of g_diff into the scalar mean.
__global__ void crf_reduce_kernel(float* __restrict__ out)
{
    __shared__ float s[CRF_B];
    const int t = threadIdx.x;
    s[t] = g_diff[t];
    __syncthreads();
#pragma unroll
    for (int stride = CRF_B / 2; stride > 0; stride >>= 1) {
        if (t < stride) s[t] += s[t + stride];
        __syncthreads();
    }
    if (t == 0) out[0] = s[0] * (1.0f / (float)CRF_B);
}

extern "C" void kernel_launch(void* const* d_in, const int* in_sizes, int n_in,
                              void* d_out, int out_size)
{
    const float* emissions = (const float*)d_in[0];
    const void*  tags      = d_in[1];
    const void*  mask      = d_in[2];
    const float* startT    = (const float*)d_in[3];
    const float* endT      = (const float*)d_in[4];
    const float* trans     = (const float*)d_in[5];
    float*       out       = (float*)d_out;

    crf_detect_kernel<<<1, 1>>>(tags, mask);
    crf_fwd_kernel<<<CRF_B, CRF_T>>>(emissions, tags, mask, startT, endT, trans);
    crf_reduce_kernel<<<1, CRF_B>>>(out);
}

// round 3
// speedup vs baseline: 1.6055x; 1.6055x over previous
#include <cuda_runtime.h>
#include <cstdint>

// Problem constants (CRF_6262062317593): B=512, S=512, T=128
#define CRF_B 512
#define CRF_S 512
#define CRF_T 128
#define SHIFT 5.0f   // ~log(T): per-step normalizer folded into exp(emission)

// Scratch (device globals: allocations are forbidden).
__device__ float g_diff[CRF_B];
__device__ int   g_tags_is64;
__device__ int   g_mask_is32;

// ---------------------------------------------------------------------------
// Detect element width of tags (int64 vs int32) and mask (int32 vs uint8).
// (Validated in R2: mask is int32 on this harness.)
// ---------------------------------------------------------------------------
__global__ void crf_detect_kernel(const void* __restrict__ tags,
                                  const void* __restrict__ mask)
{
    const unsigned int* tw = (const unsigned int*)tags;
    int zeros = 0;
    for (int k = 0; k < 64; k++)
        if (tw[2 * k + 1] == 0u) zeros++;
    g_tags_is64 = (zeros >= 48) ? 1 : 0;

    const unsigned int* mw = (const unsigned int*)mask;
    int big = 0;
    for (int k = 0; k < 64; k++)
        if (mw[k] > 1u) big++;
    g_mask_is32 = (big == 0) ? 1 : 0;
}

// ---------------------------------------------------------------------------
// Exp-space forward recursion, 2 batch elements per CTA, 128 threads.
// Thread j owns tag j for both batches. E = exp(trans) column-resident in
// registers (shared between the two batches). Per step:
//     v'[j] = (sum_i v[i] * E[i][j]) * exp(em[s][j] - SHIFT)      (if mask)
//     v'[j] = v[j]                                                 (if !mask)
// with rescale by 1/v[0] every 8 steps (logZ accumulates the normalizers).
// No per-step log/exp-of-score/max-reduction: the serial chain is
// barrier -> LDS -> FMA -> mul -> STS -> barrier.
// ---------------------------------------------------------------------------
__global__ __launch_bounds__(CRF_T, 2)
void crf_fwd_kernel(const float* __restrict__ em,       // (B,S,T) f32
                    const void*  __restrict__ tags,     // (B,S) i32 or i64
                    const void*  __restrict__ mask,     // (B,S) i32 or u8
                    const float* __restrict__ startT,   // (T)
                    const float* __restrict__ endT,     // (T)
                    const float* __restrict__ trans)    // (T,T)
{
    const int b0 = 2 * blockIdx.x;
    const int b1 = b0 + 1;
    const int j = threadIdx.x;
    const int lane = j & 31;
    const int warp = j >> 5;

    const float* __restrict__ emb0 = em + (size_t)b0 * CRF_S * CRF_T;
    const float* __restrict__ emb1 = em + (size_t)b1 * CRF_S * CRF_T;

    __shared__ float         sV0[2][CRF_T];
    __shared__ float         sV1[2][CRF_T];
    __shared__ float         sRed[8];
    __shared__ float         sPart[CRF_T];
    __shared__ int           sCnt[CRF_T];
    __shared__ unsigned char sMask0[CRF_S];
    __shared__ unsigned char sMask1[CRF_S];
    __shared__ short         sTags0[CRF_S];
    __shared__ short         sTags1[CRF_S];

    // ---- stage mask + tags with detected widths ----
    if (g_mask_is32) {
        const int* m0 = (const int*)mask + (size_t)b0 * CRF_S;
        const int* m1 = (const int*)mask + (size_t)b1 * CRF_S;
        for (int s = j; s < CRF_S; s += CRF_T) {
            sMask0[s] = (m0[s] != 0);
            sMask1[s] = (m1[s] != 0);
        }
    } else {
        const unsigned char* m0 = (const unsigned char*)mask + (size_t)b0 * CRF_S;
        const unsigned char* m1 = (const unsigned char*)mask + (size_t)b1 * CRF_S;
        for (int s = j; s < CRF_S; s += CRF_T) {
            sMask0[s] = (m0[s] != 0);
            sMask1[s] = (m1[s] != 0);
        }
    }
    if (g_tags_is64) {
        const long long* t0 = (const long long*)tags + (size_t)b0 * CRF_S;
        const long long* t1 = (const long long*)tags + (size_t)b1 * CRF_S;
        for (int s = j; s < CRF_S; s += CRF_T) {
            sTags0[s] = (short)t0[s];
            sTags1[s] = (short)t1[s];
        }
    } else {
        const int* t0 = (const int*)tags + (size_t)b0 * CRF_S;
        const int* t1 = (const int*)tags + (size_t)b1 * CRF_S;
        for (int s = j; s < CRF_S; s += CRF_T) {
            sTags0[s] = (short)t0[s];
            sTags1[s] = (short)t1[s];
        }
    }

    // ---- register-resident column j of E = exp(transitions) ----
    float Ecol[CRF_T];
#pragma unroll
    for (int i = 0; i < CRF_T; i++)
        Ecol[i] = __expf(trans[i * CRF_T + j]);

    // ---- t = 0 init: v = exp(start + em0 - m0), logZ = m0 ----
    const float m00 = startT[0] + emb0[0];   // uniform shifts (broadcast loads)
    const float m01 = startT[0] + emb1[0];
    const float stj = startT[j];
    float v0 = __expf(stj + emb0[j] - m00);
    float v1 = __expf(stj + emb1[j] - m01);
    float logZ0 = m00, logZ1 = m01;
    int   nstep0 = 0, nstep1 = 0;            // masked-in steps (SHIFT count)

    sV0[0][j] = v0;
    sV1[0][j] = v1;

    // prefetch step-1 emission weights
    float w0 = __expf(emb0[CRF_T + j] - SHIFT);
    float w1 = __expf(emb1[CRF_T + j] - SHIFT);
    __syncthreads();

    for (int s = 1; s < CRF_S; s++) {
        const int p = (s + 1) & 1;     // read buffer
        const int q = s & 1;           // write buffer

        // prefetch next emissions (off the dependency chain)
        float en0 = 0.f, en1 = 0.f;
        if (s + 1 < CRF_S) {
            en0 = emb0[(size_t)(s + 1) * CRF_T + j];
            en1 = emb1[(size_t)(s + 1) * CRF_T + j];
        }
        const int mk0 = sMask0[s];
        const int mk1 = sMask1[s];

        const float4* r0 = (const float4*)sV0[p];
        const float4* r1 = (const float4*)sV1[p];
        float a0 = 0.f, a1 = 0.f, a2 = 0.f, a3 = 0.f;
        float c0 = 0.f, c1 = 0.f, c2 = 0.f, c3 = 0.f;
#pragma unroll
        for (int i = 0; i < CRF_T / 4; i++) {
            const float4 x = r0[i];
            const float4 y = r1[i];
            a0 = fmaf(x.x, Ecol[4 * i + 0], a0);
            a1 = fmaf(x.y, Ecol[4 * i + 1], a1);
            a2 = fmaf(x.z, Ecol[4 * i + 2], a2);
            a3 = fmaf(x.w, Ecol[4 * i + 3], a3);
            c0 = fmaf(y.x, Ecol[4 * i + 0], c0);
            c1 = fmaf(y.y, Ecol[4 * i + 1], c1);
            c2 = fmaf(y.z, Ecol[4 * i + 2], c2);
            c3 = fmaf(y.w, Ecol[4 * i + 3], c3);
        }
        float dot0 = (a0 + a1) + (a2 + a3);
        float dot1 = (c0 + c1) + (c2 + c3);

        float vn0 = mk0 ? dot0 * w0 : v0;
        float vn1 = mk1 ? dot1 * w1 : v1;
        nstep0 += mk0;
        nstep1 += mk1;

        if ((s & 7) == 0) {            // periodic rescale (every 8 steps)
            const float cc0 = sV0[p][0];
            const float cc1 = sV1[p][0];
            vn0 *= (1.0f / cc0);
            vn1 *= (1.0f / cc1);
            logZ0 += __logf(cc0);
            logZ1 += __logf(cc1);
        }

        sV0[q][j] = vn0;
        sV1[q][j] = vn1;
        v0 = vn0;
        v1 = vn1;

        // next step's weights (independent of this step's results)
        w0 = __expf(en0 - SHIFT);
        w1 = __expf(en1 - SHIFT);
        __syncthreads();
    }
    logZ0 += SHIFT * (float)nstep0;
    logZ1 += SHIFT * (float)nstep1;

    // ---- final: fwd_b = log(sum_j v_j * exp(end_j)) + logZ_b ----
    const float ej = __expf(endT[j]);
    float t0 = v0 * ej;
    float t1 = v1 * ej;
#pragma unroll
    for (int off = 16; off; off >>= 1) {
        t0 += __shfl_xor_sync(0xffffffffu, t0, off);
        t1 += __shfl_xor_sync(0xffffffffu, t1, off);
    }
    if (lane == 0) { sRed[warp] = t0; sRed[4 + warp] = t1; }
    __syncthreads();
    const float fwd0 = __logf((sRed[0] + sRed[1]) + (sRed[2] + sRed[3])) + logZ0;
    const float fwd1 = __logf((sRed[4] + sRed[5]) + (sRed[6] + sRed[7])) + logZ1;

    // ---- gold scores (parallel over timesteps, fixed-order tree reduce) ----
#pragma unroll
    for (int which = 0; which < 2; which++) {
        const unsigned char* mA = which ? sMask1 : sMask0;
        const short*         tA = which ? sTags1 : sTags0;
        const float* __restrict__ eA = which ? emb1 : emb0;

        float part = 0.f;
        int cnt = 0;
        for (int s = j; s < CRF_S; s += CRF_T) {
            const int mk = mA[s] ? 1 : 0;
            cnt += mk;
            if (s >= 1 && mk) {
                const int tp = (int)tA[s - 1];
                const int tc = (int)tA[s];
                part += trans[tp * CRF_T + tc] + eA[(size_t)s * CRF_T + tc];
            }
        }
        __syncthreads();
        sPart[j] = part;
        sCnt[j]  = cnt;
        __syncthreads();
#pragma unroll
        for (int stride = CRF_T / 2; stride > 0; stride >>= 1) {
            if (j < stride) {
                sPart[j] += sPart[j + stride];
                sCnt[j]  += sCnt[j + stride];
            }
            __syncthreads();
        }
        if (j == 0) {
            const int tg0 = (int)tA[0];
            float gold = sPart[0] + startT[tg0] + eA[tg0];
            const int seq_end = sCnt[0] - 1;
            gold += endT[(int)tA[seq_end]];
            g_diff[which ? b1 : b0] = (which ? fwd1 : fwd0) - gold;
        }
    }
}

// Deterministic tree reduction of g_diff into the scalar mean.
__global__ void crf_reduce_kernel(float* __restrict__ out)
{
    __shared__ float s[CRF_B];
    const int t = threadIdx.x;
    s[t] = g_diff[t];
    __syncthreads();
#pragma unroll
    for (int stride = CRF_B / 2; stride > 0; stride >>= 1) {
        if (t < stride) s[t] += s[t + stride];
        __syncthreads();
    }
    if (t == 0) out[0] = s[0] * (1.0f / (float)CRF_B);
}

extern "C" void kernel_launch(void* const* d_in, const int* in_sizes, int n_in,
                              void* d_out, int out_size)
{
    const float* emissions = (const float*)d_in[0];
    const void*  tags      = d_in[1];
    const void*  mask      = d_in[2];
    const float* startT    = (const float*)d_in[3];
    const float* endT      = (const float*)d_in[4];
    const float* trans     = (const float*)d_in[5];
    float*       out       = (float*)d_out;

    crf_detect_kernel<<<1, 1>>>(tags, mask);
    crf_fwd_kernel<<<CRF_B / 2, CRF_T>>>(emissions, tags, mask, startT, endT, trans);
    crf_reduce_kernel<<<1, CRF_B>>>(out);
}

// round 4
// speedup vs baseline: 1.7756x; 1.1060x over previous
#include <cuda_runtime.h>
#include <cstdint>

// Problem constants (CRF_6262062317593): B=512, S=512, T=128
#define CRF_B 512
#define CRF_S 512
#define CRF_T 128
#define SHIFT 5.0f   // ~log(T): per-step normalizer folded into exp(emission)

// Scratch (device globals: allocations are forbidden).
__device__ float g_diff[CRF_B];
__device__ int   g_tags_is64;
__device__ int   g_mask_is32;

// ---- packed f32x2 helpers (Blackwell FFMA2; ptxas never auto-fuses) ----
__device__ __forceinline__ unsigned long long pk2(float lo, float hi) {
    unsigned long long r;
    asm("mov.b64 %0, {%1, %2};" : "=l"(r) : "f"(lo), "f"(hi));
    return r;
}
__device__ __forceinline__ void upk2(float& lo, float& hi, unsigned long long v) {
    asm("mov.b64 {%0, %1}, %2;" : "=f"(lo), "=f"(hi) : "l"(v));
}
__device__ __forceinline__ void fma2(unsigned long long& acc,
                                     unsigned long long a,
                                     unsigned long long b) {
    asm("fma.rn.f32x2 %0, %1, %2, %0;" : "+l"(acc) : "l"(a), "l"(b));
}

// ---------------------------------------------------------------------------
// Detect element width of tags (int64 vs int32) and mask (int32 vs uint8).
// Parallel (1 warp) to avoid a serial DRAM-latency chain.
// ---------------------------------------------------------------------------
__global__ void crf_detect_kernel(const void* __restrict__ tags,
                                  const void* __restrict__ mask)
{
    const int t = threadIdx.x;                    // 64 threads
    const unsigned int* tw = (const unsigned int*)tags;
    const unsigned int* mw = (const unsigned int*)mask;
    const int zero = (tw[2 * t + 1] == 0u) ? 1 : 0;
    const int big  = (mw[t] > 1u) ? 1 : 0;
    const unsigned zmask = __ballot_sync(0xffffffffu, zero);
    const unsigned bmask = __ballot_sync(0xffffffffu, big);
    __shared__ int sZ[2], sB[2];
    if ((t & 31) == 0) {
        sZ[t >> 5] = __popc(zmask);
        sB[t >> 5] = __popc(bmask);
    }
    __syncthreads();
    if (t == 0) {
        g_tags_is64 = ((sZ[0] + sZ[1]) >= 48) ? 1 : 0;
        g_mask_is32 = ((sB[0] + sB[1]) == 0) ? 1 : 0;
    }
}

// ---------------------------------------------------------------------------
// Exp-space forward recursion, 2 batch elements per CTA, 128 threads.
// Thread j owns tag j for both batches. E column packed as 64 f32x2 registers
// (pairs over the reduction index i). Per step:
//   v'[j] = (sum_i v[i]*E[i][j]) * exp(em[s][j]-SHIFT)  (mask) else v[j]
// Dot products run on fma.rn.f32x2 (2 MACs/lane/issue); v pairs load directly
// as ld.shared.v2.b64 (no packing movs). Rescale by 1/v[0] every 8 steps.
// ---------------------------------------------------------------------------
__global__ __launch_bounds__(CRF_T, 2)
void crf_fwd_kernel(const float* __restrict__ em,       // (B,S,T) f32
                    const void*  __restrict__ tags,     // (B,S) i32 or i64
                    const void*  __restrict__ mask,     // (B,S) i32 or u8
                    const float* __restrict__ startT,   // (T)
                    const float* __restrict__ endT,     // (T)
                    const float* __restrict__ trans)    // (T,T)
{
    const int b0 = 2 * blockIdx.x;
    const int b1 = b0 + 1;
    const int j = threadIdx.x;
    const int lane = j & 31;
    const int warp = j >> 5;

    const float* __restrict__ emb0 = em + (size_t)b0 * CRF_S * CRF_T;
    const float* __restrict__ emb1 = em + (size_t)b1 * CRF_S * CRF_T;

    __shared__ __align__(16) float sV0[2][CRF_T];
    __shared__ __align__(16) float sV1[2][CRF_T];
    __shared__ float         sRed[8];
    __shared__ float         sPart[CRF_T];
    __shared__ int           sCnt[CRF_T];
    __shared__ unsigned char sMask0[CRF_S];
    __shared__ unsigned char sMask1[CRF_S];
    __shared__ short         sTags0[CRF_S];
    __shared__ short         sTags1[CRF_S];

    // ---- stage mask + tags with detected widths ----
    if (g_mask_is32) {
        const int* m0 = (const int*)mask + (size_t)b0 * CRF_S;
        const int* m1 = (const int*)mask + (size_t)b1 * CRF_S;
        for (int s = j; s < CRF_S; s += CRF_T) {
            sMask0[s] = (m0[s] != 0);
            sMask1[s] = (m1[s] != 0);
        }
    } else {
        const unsigned char* m0 = (const unsigned char*)mask + (size_t)b0 * CRF_S;
        const unsigned char* m1 = (const unsigned char*)mask + (size_t)b1 * CRF_S;
        for (int s = j; s < CRF_S; s += CRF_T) {
            sMask0[s] = (m0[s] != 0);
            sMask1[s] = (m1[s] != 0);
        }
    }
    if (g_tags_is64) {
        const long long* t0 = (const long long*)tags + (size_t)b0 * CRF_S;
        const long long* t1 = (const long long*)tags + (size_t)b1 * CRF_S;
        for (int s = j; s < CRF_S; s += CRF_T) {
            sTags0[s] = (short)t0[s];
            sTags1[s] = (short)t1[s];
        }
    } else {
        const int* t0 = (const int*)tags + (size_t)b0 * CRF_S;
        const int* t1 = (const int*)tags + (size_t)b1 * CRF_S;
        for (int s = j; s < CRF_S; s += CRF_T) {
            sTags0[s] = (short)t0[s];
            sTags1[s] = (short)t1[s];
        }
    }

    // ---- E column j as 64 packed f32x2 registers: Epk[k]=(E[2k][j],E[2k+1][j])
    unsigned long long Epk[CRF_T / 2];
#pragma unroll
    for (int k = 0; k < CRF_T / 2; k++) {
        const float e0 = __expf(trans[(2 * k) * CRF_T + j]);
        const float e1 = __expf(trans[(2 * k + 1) * CRF_T + j]);
        Epk[k] = pk2(e0, e1);
    }

    // ---- t = 0 init: v = exp(start + em0 - m0), logZ = m0 ----
    const float m00 = startT[0] + emb0[0];   // uniform shifts (broadcast loads)
    const float m01 = startT[0] + emb1[0];
    const float stj = startT[j];
    float v0 = __expf(stj + emb0[j] - m00);
    float v1 = __expf(stj + emb1[j] - m01);
    float logZ0 = m00, logZ1 = m01;
    int   nstep0 = 0, nstep1 = 0;            // masked-in steps (SHIFT count)

    sV0[0][j] = v0;
    sV1[0][j] = v1;

    // prefetch step-1 emission weights
    float w0 = __expf(emb0[CRF_T + j] - SHIFT);
    float w1 = __expf(emb1[CRF_T + j] - SHIFT);
    __syncthreads();

    for (int s = 1; s < CRF_S; s++) {
        const int p = (s + 1) & 1;     // read buffer
        const int q = s & 1;           // write buffer

        // prefetch next emissions (off the dependency chain)
        float en0 = 0.f, en1 = 0.f;
        if (s + 1 < CRF_S) {
            en0 = emb0[(size_t)(s + 1) * CRF_T + j];
            en1 = emb1[(size_t)(s + 1) * CRF_T + j];
        }
        const int mk0 = sMask0[s];
        const int mk1 = sMask1[s];

        // v pairs load directly as 2x b64 per LDS.128 (broadcast, no conflicts)
        const ulonglong2* r0 = (const ulonglong2*)sV0[p];
        const ulonglong2* r1 = (const ulonglong2*)sV1[p];
        unsigned long long a0 = 0ull, a1 = 0ull;   // (+0,+0) packed
        unsigned long long c0 = 0ull, c1 = 0ull;
#pragma unroll
        for (int i = 0; i < CRF_T / 4; i++) {
            const ulonglong2 x = r0[i];
            const ulonglong2 y = r1[i];
            fma2(a0, x.x, Epk[2 * i + 0]);
            fma2(a1, x.y, Epk[2 * i + 1]);
            fma2(c0, y.x, Epk[2 * i + 0]);
            fma2(c1, y.y, Epk[2 * i + 1]);
        }
        float a0l, a0h, a1l, a1h, c0l, c0h, c1l, c1h;
        upk2(a0l, a0h, a0); upk2(a1l, a1h, a1);
        upk2(c0l, c0h, c0); upk2(c1l, c1h, c1);
        const float dot0 = (a0l + a0h) + (a1l + a1h);
        const float dot1 = (c0l + c0h) + (c1l + c1h);

        float vn0 = mk0 ? dot0 * w0 : v0;
        float vn1 = mk1 ? dot1 * w1 : v1;
        nstep0 += mk0;
        nstep1 += mk1;

        if ((s & 7) == 0) {            // periodic rescale (every 8 steps)
            const float cc0 = sV0[p][0];
            const float cc1 = sV1[p][0];
            vn0 *= __fdividef(1.0f, cc0);
            vn1 *= __fdividef(1.0f, cc1);
            logZ0 += __logf(cc0);
            logZ1 += __logf(cc1);
        }

        sV0[q][j] = vn0;
        sV1[q][j] = vn1;
        v0 = vn0;
        v1 = vn1;

        // next step's weights (independent of this step's results)
        w0 = __expf(en0 - SHIFT);
        w1 = __expf(en1 - SHIFT);
        __syncthreads();
    }
    logZ0 += SHIFT * (float)nstep0;
    logZ1 += SHIFT * (float)nstep1;

    // ---- final: fwd_b = log(sum_j v_j * exp(end_j)) + logZ_b ----
    const float ej = __expf(endT[j]);
    float t0 = v0 * ej;
    float t1 = v1 * ej;
#pragma unroll
    for (int off = 16; off; off >>= 1) {
        t0 += __shfl_xor_sync(0xffffffffu, t0, off);
        t1 += __shfl_xor_sync(0xffffffffu, t1, off);
    }
    if (lane == 0) { sRed[warp] = t0; sRed[4 + warp] = t1; }
    __syncthreads();
    const float fwd0 = __logf((sRed[0] + sRed[1]) + (sRed[2] + sRed[3])) + logZ0;
    const float fwd1 = __logf((sRed[4] + sRed[5]) + (sRed[6] + sRed[7])) + logZ1;

    // ---- gold scores (parallel over timesteps, fixed-order tree reduce) ----
#pragma unroll
    for (int which = 0; which < 2; which++) {
        const unsigned char* mA = which ? sMask1 : sMask0;
        const short*         tA = which ? sTags1 : sTags0;
        const float* __restrict__ eA = which ? emb1 : emb0;

        float part = 0.f;
        int cnt = 0;
        for (int s = j; s < CRF_S; s += CRF_T) {
            const int mk = mA[s] ? 1 : 0;
            cnt += mk;
            if (s >= 1 && mk) {
                const int tp = (int)tA[s - 1];
                const int tc = (int)tA[s];
                part += trans[tp * CRF_T + tc] + eA[(size_t)s * CRF_T + tc];
            }
        }
        __syncthreads();
        sPart[j] = part;
        sCnt[j]  = cnt;
        __syncthreads();
#pragma unroll
        for (int stride = CRF_T / 2; stride > 0; stride >>= 1) {
            if (j < stride) {
                sPart[j] += sPart[j + stride];
                sCnt[j]  += sCnt[j + stride];
            }
            __syncthreads();
        }
        if (j == 0) {
            const int tg0 = (int)tA[0];
            float gold = sPart[0] + startT[tg0] + eA[tg0];
            const int seq_end = sCnt[0] - 1;
            gold += endT[(int)tA[seq_end]];
            g_diff[which ? b1 : b0] = (which ? fwd1 : fwd0) - gold;
        }
    }
}

// Deterministic tree reduction of g_diff into the scalar mean.
__global__ void crf_reduce_kernel(float* __restrict__ out)
{
    __shared__ float s[CRF_B];
    const int t = threadIdx.x;
    s[t] = g_diff[t];
    __syncthreads();
#pragma unroll
    for (int stride = CRF_B / 2; stride > 0; stride >>= 1) {
        if (t < stride) s[t] += s[t + stride];
        __syncthreads();
    }
    if (t == 0) out[0] = s[0] * (1.0f / (float)CRF_B);
}

extern "C" void kernel_launch(void* const* d_in, const int* in_sizes, int n_in,
                              void* d_out, int out_size)
{
    const float* emissions = (const float*)d_in[0];
    const void*  tags      = d_in[1];
    const void*  mask      = d_in[2];
    const float* startT    = (const float*)d_in[3];
    const float* endT      = (const float*)d_in[4];
    const float* trans     = (const float*)d_in[5];
    float*       out       = (float*)d_out;

    crf_detect_kernel<<<1, 64>>>(tags, mask);
    crf_fwd_kernel<<<CRF_B / 2, CRF_T>>>(emissions, tags, mask, startT, endT, trans);
    crf_reduce_kernel<<<1, CRF_B>>>(out);
}